// round 6
// baseline (speedup 1.0000x reference)
#include <cuda_runtime.h>
#include <cstdint>

#define BB 4
#define TT 2048
#define EE 2048
#define DD 128

#define NEG_INF __int_as_float(0xff800000)

// -------- scratch (device globals: allocation-guard safe) --------
__device__ float g_Q[BB * TT * DD];
__device__ float g_K[BB * TT * DD];
__device__ float g_V[BB * TT * DD];
__device__ float g_S[(size_t)BB * TT * TT];   // 64 MB, only tiles with s_tile<=t_tile written
__device__ float g_m[BB * TT];                // per-column max
__device__ float g_r[BB * TT];                // per-column 1/sum(exp)

// ============================================================================
// Kernel 1: Q/K/V projection. C[8192,128] = x[8192,2048] @ W[2048,128]
// BM=64, BN=128, BK=16, 256 threads, 8x4 per-thread tile. grid=(128, 3)
// ============================================================================
__global__ __launch_bounds__(256) void proj_kernel(
    const float* __restrict__ x,
    const float* __restrict__ Wq,
    const float* __restrict__ Wk,
    const float* __restrict__ Wv)
{
    constexpr int BM = 64, BK = 16;
    __shared__ float As[BK][BM];     // transposed x tile
    __shared__ float Bs[BK][DD];

    const float* W = (blockIdx.y == 0) ? Wq : (blockIdx.y == 1) ? Wk : Wv;
    float* out     = (blockIdx.y == 0) ? g_Q : (blockIdx.y == 1) ? g_K : g_V;

    const int m0  = blockIdx.x * BM;
    const int tid = threadIdx.x;
    const int tm  = (tid >> 5) * 8;   // 0..56
    const int tn  = (tid & 31) * 4;   // 0..124

    // A-tile load mapping: 64 rows x 16 cols = 256 float4, 1 per thread
    const int ar  = tid >> 2;         // 0..63
    const int ac  = (tid & 3) * 4;    // 0,4,8,12
    // B-tile load mapping: 16 rows x 128 cols = 512 float4, 2 per thread
    const int br  = tid >> 5;         // 0..7 (and +8)
    const int bc  = (tid & 31) * 4;   // 0..124

    float acc[8][4] = {};

    for (int k0 = 0; k0 < EE; k0 += BK) {
        float4 av  = *(const float4*)(x + (size_t)(m0 + ar) * EE + k0 + ac);
        float4 bv0 = *(const float4*)(W + (size_t)(k0 + br)     * DD + bc);
        float4 bv1 = *(const float4*)(W + (size_t)(k0 + br + 8) * DD + bc);
        __syncthreads();
        As[ac + 0][ar] = av.x; As[ac + 1][ar] = av.y;
        As[ac + 2][ar] = av.z; As[ac + 3][ar] = av.w;
        *(float4*)&Bs[br][bc]     = bv0;
        *(float4*)&Bs[br + 8][bc] = bv1;
        __syncthreads();
        #pragma unroll
        for (int k = 0; k < BK; k++) {
            float a[8], b[4];
            *(float4*)(a)     = *(const float4*)&As[k][tm];
            *(float4*)(a + 4) = *(const float4*)&As[k][tm + 4];
            *(float4*)(b)     = *(const float4*)&Bs[k][tn];
            #pragma unroll
            for (int i = 0; i < 8; i++)
                #pragma unroll
                for (int j = 0; j < 4; j++)
                    acc[i][j] += a[i] * b[j];
        }
    }

    #pragma unroll
    for (int i = 0; i < 8; i++) {
        *(float4*)(out + (size_t)(m0 + tm + i) * DD + tn) =
            make_float4(acc[i][0], acc[i][1], acc[i][2], acc[i][3]);
    }
}

// ============================================================================
// Kernel 2: S[b,t,s] = scale * dot(Q[b,t,:], K[b,s,:]); -inf for s>t
// inside diagonal 128-tiles; upper-triangular 128-tiles skipped entirely.
// BM=BN=128, BK=16, 256 threads, 8x8 per thread. grid=(16,16,4)
// ============================================================================
__global__ __launch_bounds__(256) void score_kernel()
{
    const int bt = blockIdx.x;
    const int bs = blockIdx.y;
    if (bs > bt) return;                 // never computed, never read
    const int b  = blockIdx.z;

    constexpr int BMN = 128, BK = 16;
    __shared__ float Qs[BK][BMN];
    __shared__ float Ks[BK][BMN];

    const float* Q = g_Q + (size_t)b * TT * DD;
    const float* K = g_K + (size_t)b * TT * DD;
    const int t0 = bt * BMN, s0 = bs * BMN;

    const int tid = threadIdx.x;
    const int tm  = (tid >> 4) * 8;
    const int tn  = (tid & 15) * 8;

    // load mapping: 128 rows x 16 cols = 512 float4 -> 2 per thread
    const int lr = tid >> 2;         // 0..63 (and +64)
    const int lc = (tid & 3) * 4;    // 0,4,8,12

    float acc[8][8] = {};

    for (int k0 = 0; k0 < DD; k0 += BK) {
        float4 q0 = *(const float4*)(Q + (size_t)(t0 + lr)      * DD + k0 + lc);
        float4 q1 = *(const float4*)(Q + (size_t)(t0 + lr + 64) * DD + k0 + lc);
        float4 k0v = *(const float4*)(K + (size_t)(s0 + lr)      * DD + k0 + lc);
        float4 k1v = *(const float4*)(K + (size_t)(s0 + lr + 64) * DD + k0 + lc);
        __syncthreads();
        Qs[lc + 0][lr] = q0.x; Qs[lc + 1][lr] = q0.y; Qs[lc + 2][lr] = q0.z; Qs[lc + 3][lr] = q0.w;
        Qs[lc + 0][lr + 64] = q1.x; Qs[lc + 1][lr + 64] = q1.y; Qs[lc + 2][lr + 64] = q1.z; Qs[lc + 3][lr + 64] = q1.w;
        Ks[lc + 0][lr] = k0v.x; Ks[lc + 1][lr] = k0v.y; Ks[lc + 2][lr] = k0v.z; Ks[lc + 3][lr] = k0v.w;
        Ks[lc + 0][lr + 64] = k1v.x; Ks[lc + 1][lr + 64] = k1v.y; Ks[lc + 2][lr + 64] = k1v.z; Ks[lc + 3][lr + 64] = k1v.w;
        __syncthreads();
        #pragma unroll
        for (int k = 0; k < BK; k++) {
            float qa[8], kb[8];
            *(float4*)(qa)     = *(const float4*)&Qs[k][tm];
            *(float4*)(qa + 4) = *(const float4*)&Qs[k][tm + 4];
            *(float4*)(kb)     = *(const float4*)&Ks[k][tn];
            *(float4*)(kb + 4) = *(const float4*)&Ks[k][tn + 4];
            #pragma unroll
            for (int i = 0; i < 8; i++)
                #pragma unroll
                for (int j = 0; j < 8; j++)
                    acc[i][j] += qa[i] * kb[j];
        }
    }

    const float scale = 0.08838834764831845f;   // 1/sqrt(128)
    float* Sb = g_S + (size_t)b * TT * TT;
    #pragma unroll
    for (int i = 0; i < 8; i++) {
        const int t = t0 + tm + i;
        float v[8];
        #pragma unroll
        for (int j = 0; j < 8; j++) {
            const int s = s0 + tn + j;
            v[j] = (s > t) ? NEG_INF : acc[i][j] * scale;
        }
        *(float4*)(Sb + (size_t)t * TT + s0 + tn)     = make_float4(v[0], v[1], v[2], v[3]);
        *(float4*)(Sb + (size_t)t * TT + s0 + tn + 4) = make_float4(v[4], v[5], v[6], v[7]);
    }
}

// ============================================================================
// Kernel 3: per-column softmax stats over query axis.
// Column s: m = max_{t in [s0,T)} S[t,s], l = sum exp(S-m). Block covers one
// 128-aligned column tile so every read address lies in a written S tile;
// -inf entries (t<s, diagonal tile) contribute exp(-inf)=0 and don't hurt max.
// grid=(16,4), 128 threads
// ============================================================================
__global__ __launch_bounds__(128) void stats_kernel()
{
    const int b  = blockIdx.y;
    const int s0 = blockIdx.x * 128;
    const int s  = s0 + threadIdx.x;
    const float* Sb = g_S + (size_t)b * TT * TT;

    float m = NEG_INF;
    for (int t = s0; t < TT; t++)
        m = fmaxf(m, Sb[(size_t)t * TT + s]);

    float l = 0.0f;
    for (int t = s0; t < TT; t++)
        l += __expf(Sb[(size_t)t * TT + s] - m);   // exp(-inf - m) = 0

    g_m[b * TT + s] = m;
    g_r[b * TT + s] = 1.0f / l;                    // l >= exp(0) = 1 at t=s
}

// ============================================================================
// Kernel 4: Z[b,t,:] = sum_{s<=t} A[t,s] * V[s,:], A = exp(S-m[s]) * r[s]
// computed on the fly during the S-tile load. BM=32 (t), BK=32 (s), BN=128 (d).
// nk = blockIdx.x + 1 triangular k-tile loop. grid=(64,4), 256 threads, 4x4/thr
// ============================================================================
__global__ __launch_bounds__(256) void out_kernel(float* __restrict__ out)
{
    const int b  = blockIdx.y;
    const int t0 = blockIdx.x * 32;

    __shared__ float As[32][32];    // [s_local][t_local]
    __shared__ float Vs[32][DD];

    const float* Sb = g_S + (size_t)b * TT * TT;
    const float* Vb = g_V + (size_t)b * TT * DD;
    const float* mb = g_m + b * TT;
    const float* rb = g_r + b * TT;

    const int tid = threadIdx.x;
    const int tm  = (tid >> 5) * 4;   // 0..28
    const int tn  = (tid & 31) * 4;   // 0..124

    // S-tile load: 32x32 = 256 float4, 1 per thread
    const int sr = tid >> 3;          // 0..31 (t_local)
    const int sc = (tid & 7) * 4;     // 0..28 (s_local)

    float acc[4][4] = {};

    const int nk = blockIdx.x + 1;    // k-tiles s0 = 0..t0, step 32
    for (int kt = 0; kt < nk; kt++) {
        const int s0 = kt * 32;

        float4 sv = *(const float4*)(Sb + (size_t)(t0 + sr) * TT + s0 + sc);
        float a0 = __expf(sv.x - mb[s0 + sc + 0]) * rb[s0 + sc + 0];
        float a1 = __expf(sv.y - mb[s0 + sc + 1]) * rb[s0 + sc + 1];
        float a2 = __expf(sv.z - mb[s0 + sc + 2]) * rb[s0 + sc + 2];
        float a3 = __expf(sv.w - mb[s0 + sc + 3]) * rb[s0 + sc + 3];

        float4 vv[4];
        #pragma unroll
        for (int i = 0; i < 4; i++) {
            const int idx = tid + i * 256;
            const int vr  = idx >> 5;         // 0..31
            const int vc  = (idx & 31) * 4;   // 0..124
            vv[i] = *(const float4*)(Vb + (size_t)(s0 + vr) * DD + vc);
        }

        __syncthreads();
        As[sc + 0][sr] = a0; As[sc + 1][sr] = a1;
        As[sc + 2][sr] = a2; As[sc + 3][sr] = a3;
        #pragma unroll
        for (int i = 0; i < 4; i++) {
            const int idx = tid + i * 256;
            *(float4*)&Vs[idx >> 5][(idx & 31) * 4] = vv[i];
        }
        __syncthreads();

        #pragma unroll
        for (int k = 0; k < 32; k++) {
            float a[4], v[4];
            *(float4*)a = *(const float4*)&As[k][tm];
            *(float4*)v = *(const float4*)&Vs[k][tn];
            #pragma unroll
            for (int i = 0; i < 4; i++)
                #pragma unroll
                for (int j = 0; j < 4; j++)
                    acc[i][j] += a[i] * v[j];
        }
    }

    #pragma unroll
    for (int i = 0; i < 4; i++) {
        *(float4*)(out + (size_t)(b * TT + t0 + tm + i) * DD + tn) =
            make_float4(acc[i][0], acc[i][1], acc[i][2], acc[i][3]);
    }
}

// ============================================================================
extern "C" void kernel_launch(void* const* d_in, const int* in_sizes, int n_in,
                              void* d_out, int out_size)
{
    const float* x  = (const float*)d_in[0];
    const float* Wq = (const float*)d_in[1];
    const float* Wk = (const float*)d_in[2];
    const float* Wv = (const float*)d_in[3];
    float* out = (float*)d_out;

    proj_kernel<<<dim3(BB * TT / 64, 3), 256>>>(x, Wq, Wk, Wv);
    score_kernel<<<dim3(TT / 128, TT / 128, BB), 256>>>();
    stats_kernel<<<dim3(TT / 128, BB), 128>>>();
    out_kernel<<<dim3(TT / 32, BB), 256>>>(out);
}